// round 8
// baseline (speedup 1.0000x reference)
#include <cuda_runtime.h>
#include <cstdint>

#define MAX_E 100000
#define MAX_T 1000000
#define CCH   64
#define TPB1  128   // pass1: triplets per block
#define SCT   1024  // single-block scan threads

// Scratch (device globals — zero at module load; g_cnt/g_cursor are
// re-zeroed by k_edge at the end of every run => zero on entry always).
__device__ float4   g_rnorm4[MAX_E];
__device__ unsigned g_cnt[MAX_E];
__device__ unsigned g_off[MAX_E];
__device__ unsigned g_cursor[MAX_E];
__device__ int4     g_pack[MAX_T];   // {src, dst, cos_theta bits, 0}, CSR(dst)-ordered
__device__ int2     g_se[MAX_T];     // {src, exp(logit) bits}, CSR(dst)-ordered

// ---------------------------------------------------------------------------
// prep+count: unit bond dirs (negation cancels in src·dst dot) + degree histo
// ---------------------------------------------------------------------------
__global__ void k_prep_count(const float* __restrict__ r,
                             const int* __restrict__ tdst, int E, int T) {
    int i = blockIdx.x * blockDim.x + threadIdx.x;
    if (i < E) {
        float x = r[3 * i + 0], y = r[3 * i + 1], z = r[3 * i + 2];
        float inv = rsqrtf(x * x + y * y + z * z);
        g_rnorm4[i] = make_float4(x * inv, y * inv, z * inv, 0.0f);
    }
    if (i < T) atomicAdd(&g_cnt[tdst[i]], 1u);
}

// ---------------------------------------------------------------------------
// single-block exclusive scan: g_off = exclusive_prefix_sum(g_cnt)
// 1024 threads, each owns a contiguous chunk; shuffle-scan of chunk sums.
// ---------------------------------------------------------------------------
__global__ void __launch_bounds__(SCT)
k_scan_one(int E) {
    __shared__ unsigned wsum[32];
    int tid = threadIdx.x, lane = tid & 31, w = tid >> 5;
    int ch = (E + SCT - 1) / SCT;
    int lo = tid * ch;
    int hi = lo + ch; if (hi > E) hi = E;

    unsigned s = 0;
    for (int i = lo; i < hi; i++) s += g_cnt[i];

    unsigned x = s;
#pragma unroll
    for (int o = 1; o < 32; o <<= 1) {
        unsigned v = __shfl_up_sync(0xFFFFFFFFu, x, o);
        if (lane >= o) x += v;
    }
    if (lane == 31) wsum[w] = x;
    __syncthreads();
    if (w == 0) {
        unsigned y = wsum[lane];
#pragma unroll
        for (int o = 1; o < 32; o <<= 1) {
            unsigned v = __shfl_up_sync(0xFFFFFFFFu, y, o);
            if (lane >= o) y += v;
        }
        wsum[lane] = y;
    }
    __syncthreads();
    unsigned run = x - s + ((w > 0) ? wsum[w - 1] : 0u);

    for (int i = lo; i < hi; i++) {
        unsigned c = g_cnt[i];
        g_off[i] = run;
        run += c;
    }
}

// ---------------------------------------------------------------------------
// perm: CSR scatter of packed {src, dst, cos(theta)} (one STG.128 per triplet)
// ---------------------------------------------------------------------------
__global__ void k_perm(const int* __restrict__ tsrc, const int* __restrict__ tdst, int T) {
    int t = blockIdx.x * blockDim.x + threadIdx.x;
    if (t >= T) return;
    int s = tsrc[t], d = tdst[t];
    unsigned pos = g_off[d] + atomicAdd(&g_cursor[d], 1u);
    float4 rs = __ldg(&g_rnorm4[s]);
    float4 rd = __ldg(&g_rnorm4[d]);
    float cth = rs.x * rd.x + rs.y * rd.y + rs.z * rd.z;
    cth = fminf(fmaxf(cth, -1.0f + 1e-6f), 1.0f - 1e-6f);
    g_pack[pos] = make_int4(s, d, __float_as_int(cth), 0);
}

// ---------------------------------------------------------------------------
// pass1: exp(logit) in CSR order.
//  - xij[src] staged to smem (coalesced, odd stride 65 => conflict-free)
//  - xij[dst] direct (CSR adjacency -> few distinct rows/warp, L1-hits)
//  - Chebyshev 3-term recurrence (1 FMA/channel)
//  - writes {src, exp(a)} packed; softmax needs no max subtraction
//    (|a| << 88, alpha identical — validated R4-R7, rel_err 6.6e-6)
// ---------------------------------------------------------------------------
__global__ void __launch_bounds__(TPB1)
k_pass1(const float* __restrict__ xij, const float* __restrict__ attn, int T) {
    __shared__ float sx[TPB1 * 65];
    __shared__ float sat[CCH];
    int tid = threadIdx.x;
    int base = blockIdx.x * TPB1;
    if (tid < CCH) sat[tid] = attn[tid];

    int lane = tid & 31, w = tid >> 5;
    for (int j = w; j < TPB1; j += TPB1 / 32) {
        int t = base + j;
        if (t < T) {
            int s = __ldg(&g_pack[t].x);
            float2 v = __ldg((const float2*)(xij + (size_t)s * CCH) + lane);
            sx[j * 65 + 2 * lane]     = v.x;
            sx[j * 65 + 2 * lane + 1] = v.y;
        }
    }
    __syncthreads();

    int t = base + tid;
    if (t >= T) return;

    int4 p = __ldg(&g_pack[t]);
    int d = p.y;
    float cth = __int_as_float(p.z);
    float c2 = 2.0f * cth;
    float zp = cth, zc = 1.0f;   // T_{-1}, T_0

    const float4* xd = (const float4*)(xij + (size_t)d * CCH);
    const float* row = &sx[tid * 65];
    float a = 0.0f;

#pragma unroll
    for (int k = 0; k < CCH / 4; k++) {
        float4 D = __ldg(xd + k);
        float dv[4] = {D.x, D.y, D.z, D.w};
#pragma unroll
        for (int j = 0; j < 4; j++) {
            int c = 4 * k + j;
            float v = zc + row[c] + dv[j];
            float e = __fdividef(v, 1.0f + __expf(-v));   // silu
            a = fmaf(e, sat[c], a);
            float zn = fmaf(c2, zc, -zp);                 // Chebyshev step
            zp = zc; zc = zn;
        }
    }
    g_se[t] = make_int2(p.x, __float_as_int(__expf(a)));  // coalesced STG.64
}

// ---------------------------------------------------------------------------
// edge: warp-per-edge aggregate: ft = (sum ex*x[src]) / sum ex.
// Lane owns channels {2*lane, 2*lane+1} (float2 loads/stores).
// Restores g_cnt / g_cursor to zero for the next run.
// ---------------------------------------------------------------------------
__global__ void __launch_bounds__(256)
k_edge(const float* __restrict__ xij, float* __restrict__ ft, int E) {
    int warp = (blockIdx.x * blockDim.x + threadIdx.x) >> 5;
    int lane = threadIdx.x & 31;
    if (warp >= E) return;

    int base = (int)g_off[warp];
    int deg  = (int)g_cnt[warp];
    if (lane == 0) { g_cnt[warp] = 0u; g_cursor[warp] = 0u; }

    float ax = 0.0f, ay = 0.0f, den = 0.0f;

    int i = 0;
    for (; i + 4 <= deg; i += 4) {
        int2 p0 = __ldg(&g_se[base + i + 0]);
        int2 p1 = __ldg(&g_se[base + i + 1]);
        int2 p2 = __ldg(&g_se[base + i + 2]);
        int2 p3 = __ldg(&g_se[base + i + 3]);
        float2 v0 = __ldg((const float2*)(xij + (size_t)p0.x * CCH) + lane);
        float2 v1 = __ldg((const float2*)(xij + (size_t)p1.x * CCH) + lane);
        float2 v2 = __ldg((const float2*)(xij + (size_t)p2.x * CCH) + lane);
        float2 v3 = __ldg((const float2*)(xij + (size_t)p3.x * CCH) + lane);
        float e0 = __int_as_float(p0.y), e1 = __int_as_float(p1.y);
        float e2 = __int_as_float(p2.y), e3 = __int_as_float(p3.y);
        den += (e0 + e1) + (e2 + e3);
        ax = fmaf(e0, v0.x, ax); ay = fmaf(e0, v0.y, ay);
        ax = fmaf(e1, v1.x, ax); ay = fmaf(e1, v1.y, ay);
        ax = fmaf(e2, v2.x, ax); ay = fmaf(e2, v2.y, ay);
        ax = fmaf(e3, v3.x, ax); ay = fmaf(e3, v3.y, ay);
    }
    for (; i < deg; i++) {
        int2 p0 = __ldg(&g_se[base + i]);
        float2 v0 = __ldg((const float2*)(xij + (size_t)p0.x * CCH) + lane);
        float e0 = __int_as_float(p0.y);
        den += e0;
        ax = fmaf(e0, v0.x, ax); ay = fmaf(e0, v0.y, ay);
    }

    float inv = (deg > 0) ? __fdividef(1.0f, den) : 0.0f;
    *((float2*)(ft + (size_t)warp * CCH) + lane) = make_float2(ax * inv, ay * inv);
}

// ---------------------------------------------------------------------------
extern "C" void kernel_launch(void* const* d_in, const int* in_sizes, int n_in,
                              void* d_out, int out_size) {
    const float* xij  = (const float*)d_in[0];
    const float* r    = (const float*)d_in[1];
    const float* attn = (const float*)d_in[2];
    const int*   tsrc = (const int*)d_in[3];
    const int*   tdst = (const int*)d_in[4];
    float* ft = (float*)d_out;

    int E = in_sizes[1] / 3;
    int T = in_sizes[3];
    int nmx = (T > E) ? T : E;

    k_prep_count<<<(nmx + 255) / 256, 256>>>(r, tdst, E, T);
    k_scan_one  <<<1, SCT>>>(E);
    k_perm      <<<(T + 255) / 256, 256>>>(tsrc, tdst, T);
    k_pass1     <<<(T + TPB1 - 1) / TPB1, TPB1>>>(xij, attn, T);
    k_edge      <<<(E * 32 + 255) / 256, 256>>>(xij, ft, E);
}

// round 10
// speedup vs baseline: 1.3396x; 1.3396x over previous
#include <cuda_runtime.h>
#include <cstdint>

#define MAX_E 100000
#define MAX_T 1000000
#define CCH   64
#define SCAN_BLK 512
#define MAX_SCAN_BLOCKS ((MAX_E + SCAN_BLK - 1) / SCAN_BLK)
#define TPB1  128   // pass1: CSR slots per block
#define RS    65    // padded smem row stride (odd => conflict-free)

// Scratch (device globals — zero at module load; g_cnt/g_cursor re-zeroed by
// k_edge at the end of every run => zero on entry for every replay).
__device__ float4   g_rnorm4[MAX_E];
__device__ unsigned g_cnt[MAX_E];
__device__ unsigned g_off[MAX_E];
__device__ unsigned g_cursor[MAX_E];
__device__ unsigned g_bsum[MAX_SCAN_BLOCKS];
__device__ int4     g_pack[MAX_T];   // {src, dst, cos_theta bits, 0}, CSR-ordered
__device__ int2     g_se[MAX_T];     // {src, exp(logit) bits}, CSR-ordered

// ---------------------------------------------------------------------------
__global__ void k_prep_count(const float* __restrict__ r,
                             const int* __restrict__ tdst, int E, int T) {
    int i = blockIdx.x * blockDim.x + threadIdx.x;
    if (i < E) {
        float x = r[3 * i + 0], y = r[3 * i + 1], z = r[3 * i + 2];
        float inv = rsqrtf(x * x + y * y + z * z);
        g_rnorm4[i] = make_float4(x * inv, y * inv, z * inv, 0.0f);
    }
    if (i < T) atomicAdd(&g_cnt[tdst[i]], 1u);
}

// ------------------- 3-kernel exclusive scan (R5, proven) ------------------
__global__ void k_scan1(int E) {
    __shared__ unsigned sh[SCAN_BLK];
    int i = blockIdx.x * SCAN_BLK + threadIdx.x;
    unsigned v = (i < E) ? g_cnt[i] : 0u;
    sh[threadIdx.x] = v;
    __syncthreads();
    unsigned incl = v;
    for (int ofs = 1; ofs < SCAN_BLK; ofs <<= 1) {
        unsigned add = (threadIdx.x >= ofs) ? sh[threadIdx.x - ofs] : 0u;
        __syncthreads();
        incl += add;
        sh[threadIdx.x] = incl;
        __syncthreads();
    }
    if (i < E) g_off[i] = incl - v;
    if (threadIdx.x == SCAN_BLK - 1) g_bsum[blockIdx.x] = incl;
}

__global__ void k_scan2(int nb) {
    __shared__ unsigned sh[SCAN_BLK];
    unsigned v = (threadIdx.x < nb) ? g_bsum[threadIdx.x] : 0u;
    sh[threadIdx.x] = v;
    __syncthreads();
    unsigned incl = v;
    for (int ofs = 1; ofs < SCAN_BLK; ofs <<= 1) {
        unsigned add = (threadIdx.x >= ofs) ? sh[threadIdx.x - ofs] : 0u;
        __syncthreads();
        incl += add;
        sh[threadIdx.x] = incl;
        __syncthreads();
    }
    if (threadIdx.x < nb) g_bsum[threadIdx.x] = incl - v;
}

__global__ void k_scan3(int E) {
    int i = blockIdx.x * SCAN_BLK + threadIdx.x;
    if (i < E) g_off[i] += g_bsum[blockIdx.x];
}

// ---------------------------------------------------------------------------
// perm: CSR scatter of packed {src, dst, cos(theta)} (one STG.128 per triplet)
// ---------------------------------------------------------------------------
__global__ void k_perm(const int* __restrict__ tsrc, const int* __restrict__ tdst, int T) {
    int t = blockIdx.x * blockDim.x + threadIdx.x;
    if (t >= T) return;
    int s = tsrc[t], d = tdst[t];
    unsigned pos = g_off[d] + atomicAdd(&g_cursor[d], 1u);
    float4 rs = __ldg(&g_rnorm4[s]);
    float4 rd = __ldg(&g_rnorm4[d]);
    float cth = rs.x * rd.x + rs.y * rd.y + rs.z * rd.z;
    cth = fminf(fmaxf(cth, -1.0f + 1e-6f), 1.0f - 1e-6f);
    g_pack[pos] = make_int4(s, d, __float_as_int(cth), 0);
}

// ---------------------------------------------------------------------------
// pass1: exp(logit) per CSR slot.
//  A) stage SUM rows (xij[src]+xij[dst]) into smem — both gathers are
//     warp-cooperative & coalesced (dst contiguous in CSR order).
//  B) thread-per-slot: Chebyshev 3-term recurrence (1 FMA/ch; 4 updates per
//     4-channel group — T_{c}..T_{c+3} consumed, T_{c+4} handed to next group)
//     + silu with 4-way batched reciprocal (1 RCP per 4 channels).
//  No softmax max subtraction (|logit| << 88; alpha identical — R4-R8).
// ---------------------------------------------------------------------------
__global__ void __launch_bounds__(TPB1)
k_pass1(const float* __restrict__ xij, const float* __restrict__ attn, int T) {
    __shared__ float sx[TPB1 * RS];
    __shared__ float sat[CCH];
    int tid = threadIdx.x;
    int base = blockIdx.x * TPB1;
    if (tid < CCH) sat[tid] = attn[tid];

    int lane = tid & 31, w = tid >> 5;
    for (int j = w; j < TPB1; j += TPB1 / 32) {
        int t = base + j;
        if (t < T) {
            int s = __ldg(&g_pack[t].x);   // uniform across warp -> broadcast
            int d = __ldg(&g_pack[t].y);
            float2 a = __ldg((const float2*)(xij + (size_t)s * CCH) + lane);
            float2 b = __ldg((const float2*)(xij + (size_t)d * CCH) + lane);
            sx[j * RS + 2 * lane]     = a.x + b.x;
            sx[j * RS + 2 * lane + 1] = a.y + b.y;
        }
    }
    __syncthreads();

    int t = base + tid;
    if (t >= T) return;

    int4 p = __ldg(&g_pack[t]);
    float cth = __int_as_float(p.z);
    float c2 = 2.0f * cth;
    float zp = cth, zc = 1.0f;   // T_{-1}, T_0

    const float* row = &sx[tid * RS];
    const float LOG2E = 1.4426950408889634f;
    float a = 0.0f;

#pragma unroll
    for (int k = 0; k < CCH / 4; k++) {
        // Chebyshev values T_{4k}..T_{4k+3}; 4 recurrence updates per group
        float v0 = zc + row[4 * k + 0];
        float z1 = fmaf(c2, zc, -zp);
        float v1 = z1 + row[4 * k + 1];
        float z2 = fmaf(c2, z1, -zc);
        float v2 = z2 + row[4 * k + 2];
        float z3 = fmaf(c2, z2, -z1);
        float v3 = z3 + row[4 * k + 3];
        float z4 = fmaf(c2, z3, -z2);
        zp = z3; zc = z4;                 // next group starts at T_{4k+4}

        // silu via 4-way batched reciprocal: 4 EX2 + 1 RCP
        float A = 1.0f + exp2f(-v0 * LOG2E);
        float B = 1.0f + exp2f(-v1 * LOG2E);
        float C = 1.0f + exp2f(-v2 * LOG2E);
        float D = 1.0f + exp2f(-v3 * LOG2E);
        float AB = A * B, CD = C * D;
        float rall = __fdividef(1.0f, AB * CD);
        float rAB = rall * CD, rCD = rall * AB;
        float e0 = v0 * (B * rAB);
        float e1 = v1 * (A * rAB);
        float e2 = v2 * (D * rCD);
        float e3 = v3 * (C * rCD);

        a = fmaf(e0, sat[4 * k + 0], a);
        a = fmaf(e1, sat[4 * k + 1], a);
        a = fmaf(e2, sat[4 * k + 2], a);
        a = fmaf(e3, sat[4 * k + 3], a);
    }
    g_se[t] = make_int2(p.x, __float_as_int(__expf(a)));  // coalesced STG.64
}

// ---------------------------------------------------------------------------
// edge: warp-per-edge aggregate: ft = (sum ex*x[src]) / sum ex.
// Lane owns channels {2*lane, 2*lane+1}. Restores g_cnt/g_cursor to zero.
// ---------------------------------------------------------------------------
__global__ void __launch_bounds__(256)
k_edge(const float* __restrict__ xij, float* __restrict__ ft, int E) {
    int warp = (blockIdx.x * blockDim.x + threadIdx.x) >> 5;
    int lane = threadIdx.x & 31;
    if (warp >= E) return;

    int base = (int)g_off[warp];
    int deg  = (int)g_cnt[warp];
    if (lane == 0) { g_cnt[warp] = 0u; g_cursor[warp] = 0u; }

    float ax = 0.0f, ay = 0.0f, den = 0.0f;

    int i = 0;
    for (; i + 4 <= deg; i += 4) {
        int2 p0 = __ldg(&g_se[base + i + 0]);
        int2 p1 = __ldg(&g_se[base + i + 1]);
        int2 p2 = __ldg(&g_se[base + i + 2]);
        int2 p3 = __ldg(&g_se[base + i + 3]);
        float2 v0 = __ldg((const float2*)(xij + (size_t)p0.x * CCH) + lane);
        float2 v1 = __ldg((const float2*)(xij + (size_t)p1.x * CCH) + lane);
        float2 v2 = __ldg((const float2*)(xij + (size_t)p2.x * CCH) + lane);
        float2 v3 = __ldg((const float2*)(xij + (size_t)p3.x * CCH) + lane);
        float e0 = __int_as_float(p0.y), e1 = __int_as_float(p1.y);
        float e2 = __int_as_float(p2.y), e3 = __int_as_float(p3.y);
        den += (e0 + e1) + (e2 + e3);
        ax = fmaf(e0, v0.x, ax); ay = fmaf(e0, v0.y, ay);
        ax = fmaf(e1, v1.x, ax); ay = fmaf(e1, v1.y, ay);
        ax = fmaf(e2, v2.x, ax); ay = fmaf(e2, v2.y, ay);
        ax = fmaf(e3, v3.x, ax); ay = fmaf(e3, v3.y, ay);
    }
    for (; i < deg; i++) {
        int2 p0 = __ldg(&g_se[base + i]);
        float2 v0 = __ldg((const float2*)(xij + (size_t)p0.x * CCH) + lane);
        float e0 = __int_as_float(p0.y);
        den += e0;
        ax = fmaf(e0, v0.x, ax); ay = fmaf(e0, v0.y, ay);
    }

    float inv = (deg > 0) ? __fdividef(1.0f, den) : 0.0f;
    *((float2*)(ft + (size_t)warp * CCH) + lane) = make_float2(ax * inv, ay * inv);
}

// ---------------------------------------------------------------------------
extern "C" void kernel_launch(void* const* d_in, const int* in_sizes, int n_in,
                              void* d_out, int out_size) {
    const float* xij  = (const float*)d_in[0];
    const float* r    = (const float*)d_in[1];
    const float* attn = (const float*)d_in[2];
    const int*   tsrc = (const int*)d_in[3];
    const int*   tdst = (const int*)d_in[4];
    float* ft = (float*)d_out;

    int E = in_sizes[1] / 3;
    int T = in_sizes[3];
    int nsb = (E + SCAN_BLK - 1) / SCAN_BLK;
    int nmx = (T > E) ? T : E;

    k_prep_count<<<(nmx + 255) / 256, 256>>>(r, tdst, E, T);
    k_scan1<<<nsb, SCAN_BLK>>>(E);
    k_scan2<<<1,   SCAN_BLK>>>(nsb);
    k_scan3<<<nsb, SCAN_BLK>>>(E);
    k_perm <<<(T + 255) / 256, 256>>>(tsrc, tdst, T);
    k_pass1<<<(T + TPB1 - 1) / TPB1, TPB1>>>(xij, attn, T);
    k_edge <<<(E * 32 + 255) / 256, 256>>>(xij, ft, E);
}

// round 11
// speedup vs baseline: 1.5342x; 1.1453x over previous
#include <cuda_runtime.h>
#include <cstdint>

#define MAX_E 100000
#define MAX_T 1000000
#define CCH   64
#define SCAN_BLK 512
#define MAX_SCAN_BLOCKS ((MAX_E + SCAN_BLK - 1) / SCAN_BLK)
#define TPB1  128   // pass1: CSR slots per block
#define RS    65    // padded smem row stride (odd => conflict-free)

// Scratch (device globals — zero at module load; g_cnt/g_cursor re-zeroed by
// k_edge at the end of every run => zero on entry for every replay).
__device__ float4   g_rnorm4[MAX_E];
__device__ unsigned g_cnt[MAX_E];
__device__ unsigned g_off[MAX_E];    // block-local exclusive prefix (scan1)
__device__ unsigned g_cursor[MAX_E];
__device__ unsigned g_bsum[MAX_SCAN_BLOCKS];  // block offsets (scan2)
__device__ int4     g_pack[MAX_T];   // {src, dst, cos_theta bits, 0}, CSR-ordered
__device__ int2     g_se[MAX_T];     // {src, exp(logit) bits}, CSR-ordered

// ---------------------------------------------------------------------------
__global__ void k_prep_count(const float* __restrict__ r,
                             const int* __restrict__ tdst, int E, int T) {
    int i = blockIdx.x * blockDim.x + threadIdx.x;
    if (i < E) {
        float x = r[3 * i + 0], y = r[3 * i + 1], z = r[3 * i + 2];
        float inv = rsqrtf(x * x + y * y + z * z);
        g_rnorm4[i] = make_float4(x * inv, y * inv, z * inv, 0.0f);
    }
    if (i < T) atomicAdd(&g_cnt[tdst[i]], 1u);
}

// -------- 2-kernel scan; the final block-offset add is folded into consumers
__global__ void k_scan1(int E) {
    __shared__ unsigned sh[SCAN_BLK];
    int i = blockIdx.x * SCAN_BLK + threadIdx.x;
    unsigned v = (i < E) ? g_cnt[i] : 0u;
    sh[threadIdx.x] = v;
    __syncthreads();
    unsigned incl = v;
    for (int ofs = 1; ofs < SCAN_BLK; ofs <<= 1) {
        unsigned add = (threadIdx.x >= ofs) ? sh[threadIdx.x - ofs] : 0u;
        __syncthreads();
        incl += add;
        sh[threadIdx.x] = incl;
        __syncthreads();
    }
    if (i < E) g_off[i] = incl - v;          // block-local exclusive
    if (threadIdx.x == SCAN_BLK - 1) g_bsum[blockIdx.x] = incl;
}

__global__ void k_scan2(int nb) {
    __shared__ unsigned sh[SCAN_BLK];
    unsigned v = (threadIdx.x < nb) ? g_bsum[threadIdx.x] : 0u;
    sh[threadIdx.x] = v;
    __syncthreads();
    unsigned incl = v;
    for (int ofs = 1; ofs < SCAN_BLK; ofs <<= 1) {
        unsigned add = (threadIdx.x >= ofs) ? sh[threadIdx.x - ofs] : 0u;
        __syncthreads();
        incl += add;
        sh[threadIdx.x] = incl;
        __syncthreads();
    }
    if (threadIdx.x < nb) g_bsum[threadIdx.x] = incl - v;   // exclusive blocks
}

__device__ __forceinline__ unsigned edge_base(int e) {
    return g_off[e] + g_bsum[e >> 9];        // SCAN_BLK == 512
}

// ---------------------------------------------------------------------------
// perm: CSR scatter of packed {src, dst, cos(theta)} (one STG.128 per triplet)
// ---------------------------------------------------------------------------
__global__ void k_perm(const int* __restrict__ tsrc, const int* __restrict__ tdst, int T) {
    int t = blockIdx.x * blockDim.x + threadIdx.x;
    if (t >= T) return;
    int s = tsrc[t], d = tdst[t];
    unsigned pos = edge_base(d) + atomicAdd(&g_cursor[d], 1u);
    float4 rs = __ldg(&g_rnorm4[s]);
    float4 rd = __ldg(&g_rnorm4[d]);
    float cth = rs.x * rd.x + rs.y * rd.y + rs.z * rd.z;
    cth = fminf(fmaxf(cth, -1.0f + 1e-6f), 1.0f - 1e-6f);
    g_pack[pos] = make_int4(s, d, __float_as_int(cth), 0);
}

// ---------------------------------------------------------------------------
// pass1: exp(logit) per CSR slot.
//  A) stage SUM rows (xij[src]+xij[dst]) into smem (coalesced; dst rows for
//     consecutive slots repeat/advance -> L1-friendly)
//  B) thread-per-slot, zero global loads: Chebyshev 3-term recurrence
//     (1 FMA/ch) + silu via fast intrinsics (__expf -> MUFU.EX2, __fdividef
//     -> MUFU.RCP — the proven R5 formulation).
//  No softmax max subtraction (|logit| << 88; alpha identical — R4-R10).
// ---------------------------------------------------------------------------
__global__ void __launch_bounds__(TPB1)
k_pass1(const float* __restrict__ xij, const float* __restrict__ attn, int T) {
    __shared__ float sx[TPB1 * RS];
    __shared__ float sat[CCH];
    int tid = threadIdx.x;
    int base = blockIdx.x * TPB1;
    if (tid < CCH) sat[tid] = attn[tid];

    int lane = tid & 31, w = tid >> 5;
    for (int j = w; j < TPB1; j += TPB1 / 32) {
        int t = base + j;
        if (t < T) {
            int s = __ldg(&g_pack[t].x);   // warp-uniform -> broadcast
            int d = __ldg(&g_pack[t].y);
            float2 a = __ldg((const float2*)(xij + (size_t)s * CCH) + lane);
            float2 b = __ldg((const float2*)(xij + (size_t)d * CCH) + lane);
            sx[j * RS + 2 * lane]     = a.x + b.x;
            sx[j * RS + 2 * lane + 1] = a.y + b.y;
        }
    }
    __syncthreads();

    int t = base + tid;
    if (t >= T) return;

    int4 p = __ldg(&g_pack[t]);
    float cth = __int_as_float(p.z);
    float c2 = 2.0f * cth;
    float zp = cth, zc = 1.0f;   // T_{-1}, T_0

    const float* row = &sx[tid * RS];
    float a = 0.0f;

#pragma unroll
    for (int c = 0; c < CCH; c++) {
        float v = zc + row[c];
        float e = __fdividef(v, 1.0f + __expf(-v));   // silu (fast intrinsics)
        a = fmaf(e, sat[c], a);
        float zn = fmaf(c2, zc, -zp);                 // Chebyshev step
        zp = zc; zc = zn;
    }
    g_se[t] = make_int2(p.x, __float_as_int(__expf(a)));  // coalesced STG.64
}

// ---------------------------------------------------------------------------
// edge: warp-per-edge aggregate: ft = (sum ex*x[src]) / sum ex.
// Lane owns channels {2*lane, 2*lane+1}. Restores g_cnt/g_cursor to zero.
// ---------------------------------------------------------------------------
__global__ void __launch_bounds__(256)
k_edge(const float* __restrict__ xij, float* __restrict__ ft, int E) {
    int warp = (blockIdx.x * blockDim.x + threadIdx.x) >> 5;
    int lane = threadIdx.x & 31;
    if (warp >= E) return;

    int base = (int)edge_base(warp);
    int deg  = (int)g_cnt[warp];
    if (lane == 0) { g_cnt[warp] = 0u; g_cursor[warp] = 0u; }

    float ax = 0.0f, ay = 0.0f, den = 0.0f;

    int i = 0;
    for (; i + 4 <= deg; i += 4) {
        int2 p0 = __ldg(&g_se[base + i + 0]);
        int2 p1 = __ldg(&g_se[base + i + 1]);
        int2 p2 = __ldg(&g_se[base + i + 2]);
        int2 p3 = __ldg(&g_se[base + i + 3]);
        float2 v0 = __ldg((const float2*)(xij + (size_t)p0.x * CCH) + lane);
        float2 v1 = __ldg((const float2*)(xij + (size_t)p1.x * CCH) + lane);
        float2 v2 = __ldg((const float2*)(xij + (size_t)p2.x * CCH) + lane);
        float2 v3 = __ldg((const float2*)(xij + (size_t)p3.x * CCH) + lane);
        float e0 = __int_as_float(p0.y), e1 = __int_as_float(p1.y);
        float e2 = __int_as_float(p2.y), e3 = __int_as_float(p3.y);
        den += (e0 + e1) + (e2 + e3);
        ax = fmaf(e0, v0.x, ax); ay = fmaf(e0, v0.y, ay);
        ax = fmaf(e1, v1.x, ax); ay = fmaf(e1, v1.y, ay);
        ax = fmaf(e2, v2.x, ax); ay = fmaf(e2, v2.y, ay);
        ax = fmaf(e3, v3.x, ax); ay = fmaf(e3, v3.y, ay);
    }
    for (; i < deg; i++) {
        int2 p0 = __ldg(&g_se[base + i]);
        float2 v0 = __ldg((const float2*)(xij + (size_t)p0.x * CCH) + lane);
        float e0 = __int_as_float(p0.y);
        den += e0;
        ax = fmaf(e0, v0.x, ax); ay = fmaf(e0, v0.y, ay);
    }

    float inv = (deg > 0) ? __fdividef(1.0f, den) : 0.0f;
    *((float2*)(ft + (size_t)warp * CCH) + lane) = make_float2(ax * inv, ay * inv);
}

// ---------------------------------------------------------------------------
extern "C" void kernel_launch(void* const* d_in, const int* in_sizes, int n_in,
                              void* d_out, int out_size) {
    const float* xij  = (const float*)d_in[0];
    const float* r    = (const float*)d_in[1];
    const float* attn = (const float*)d_in[2];
    const int*   tsrc = (const int*)d_in[3];
    const int*   tdst = (const int*)d_in[4];
    float* ft = (float*)d_out;

    int E = in_sizes[1] / 3;
    int T = in_sizes[3];
    int nsb = (E + SCAN_BLK - 1) / SCAN_BLK;
    int nmx = (T > E) ? T : E;

    k_prep_count<<<(nmx + 255) / 256, 256>>>(r, tdst, E, T);
    k_scan1<<<nsb, SCAN_BLK>>>(E);
    k_scan2<<<1,   SCAN_BLK>>>(nsb);
    k_perm <<<(T + 255) / 256, 256>>>(tsrc, tdst, T);
    k_pass1<<<(T + TPB1 - 1) / TPB1, TPB1>>>(xij, attn, T);
    k_edge <<<(E * 32 + 255) / 256, 256>>>(xij, ft, E);
}